// round 11
// baseline (speedup 1.0000x reference)
#include <cuda_runtime.h>
#include <cstdint>

// Problem constants
#define SQ   2048        // sequence length
#define DK   64          // head dim
#define NBH  64          // B*H = 4*16
#define NB   4           // batch
#define TM   16          // query rows per CTA
#define TN   256         // key/value columns per tile
#define NTHREADS 256
#define NTILES (SQ / TN) // 8

// Canonical mask: 1 byte per element, [B][S]. Filled by mask_canon_kernel.
__device__ unsigned char g_mask[NB * SQ];

// ---------------------------------------------------------------------------
// Mask canonicalization (dtype-agnostic -> uint8 0/1). Unchanged from R7.
// ---------------------------------------------------------------------------
__global__ void mask_canon_kernel(const unsigned char* __restrict__ mraw)
{
    __shared__ int flagGT1, flagOff;
    const int tid = threadIdx.x;
    if (tid == 0) { flagGT1 = 0; flagOff = 0; }
    __syncthreads();

    int lGT1 = 0, lOff = 0;
    for (int i = tid; i < NB * SQ; i += NTHREADS) {
        unsigned char b = mraw[i];
        if (b > 1)        lGT1 = 1;
        if ((i & 3) && b) lOff = 1;
    }
    if (lGT1) atomicOr(&flagGT1, 1);
    if (lOff) atomicOr(&flagOff, 1);
    __syncthreads();

    if (flagGT1) {
        const float* mf = reinterpret_cast<const float*>(mraw);
        for (int i = tid; i < NB * SQ; i += NTHREADS)
            g_mask[i] = (mf[i] != 0.0f) ? 1 : 0;
    } else if (flagOff) {
        for (int i = tid; i < NB * SQ; i += NTHREADS)
            g_mask[i] = mraw[i] ? 1 : 0;
    } else {
        const int* mi = reinterpret_cast<const int*>(mraw);
        for (int i = tid; i < NB * SQ; i += NTHREADS)
            g_mask[i] = (mi[i] != 0) ? 1 : 0;
    }
}

// Shared memory layout (~197 KB)
struct Smem {
    float sS[TM][SQ];      // 131072 B : scores -> p = exp(s - m)
    float sKV[TN * DK];    //  65536 B : K tile [d][t] (64x256) OR V tile [t][d] (256x64)
                           //            also reused as partial buffer [4][16][64] in phase 3
    float sQt[DK][18];     //   4608 B : Q tile transposed, padded stride 18
    float sInv[TM];        // 1/l per row
};

__global__ __launch_bounds__(NTHREADS, 1)
void sdpa_fp32_kernel(const float* __restrict__ q,
                      const float* __restrict__ k,
                      const float* __restrict__ v,
                      float* __restrict__ out_ctx,
                      float* __restrict__ out_attn)
{
    extern __shared__ char smem_raw[];
    Smem& sm = *reinterpret_cast<Smem*>(smem_raw);

    const int bh   = blockIdx.y;           // 0..63
    const int row0 = blockIdx.x * TM;      // query row block
    const int b    = bh >> 4;              // batch index (H=16)
    const int tid  = threadIdx.x;

    const float* __restrict__ Q  = q + (size_t)bh * SQ * DK;
    const float* __restrict__ K  = k + (size_t)bh * DK * SQ;   // [d][t]
    const float* __restrict__ V  = v + (size_t)bh * SQ * DK;
    const unsigned char* __restrict__ Mk = g_mask + (size_t)b * SQ;

    // ---------- Load Q tile (16 x 64) transposed into sQt[d][r] ----------
    {
        int r  = tid & 15;          // 0..15
        int d0 = (tid >> 4) * 4;    // 0,4,...,60
        float4 qv = *reinterpret_cast<const float4*>(Q + (size_t)(row0 + r) * DK + d0);
        sm.sQt[d0 + 0][r] = qv.x;
        sm.sQt[d0 + 1][r] = qv.y;
        sm.sQt[d0 + 2][r] = qv.z;
        sm.sQt[d0 + 3][r] = qv.w;
    }

    // ---------- Phase 1: scores = (Q K) * scale, masked -> sS ----------
    // Per-thread micro-tile: 2 rows x 8 cols. 8 row-groups x 32 col-groups.
    {
        const int rowg = tid >> 5;        // 0..7  -> rows rowg*2, rowg*2+1
        const int colg = tid & 31;        // 0..31 -> cols colg*8 .. +7
        const int r0   = rowg * 2;
        const int c0   = colg * 8;
        const float scale = 0.125f;       // 1/sqrt(64)

        for (int jt = 0; jt < NTILES; ++jt) {
            const int t0 = jt * TN;
            __syncthreads();  // prev consumers done with sKV (covers Q-load on jt=0)
            // load K tile: 64 (d) x 256 (t), coalesced float4
            #pragma unroll
            for (int i = tid; i < (DK * TN) / 4; i += NTHREADS) {
                int d  = i >> 6;               // 64 float4 per row
                int c4 = (i & 63) << 2;
                *reinterpret_cast<float4*>(&sm.sKV[d * TN + c4]) =
                    *reinterpret_cast<const float4*>(K + (size_t)d * SQ + t0 + c4);
            }
            __syncthreads();

            float a00=0.f,a01=0.f,a02=0.f,a03=0.f,a04=0.f,a05=0.f,a06=0.f,a07=0.f;
            float a10=0.f,a11=0.f,a12=0.f,a13=0.f,a14=0.f,a15=0.f,a16=0.f,a17=0.f;
            #pragma unroll 8
            for (int d = 0; d < DK; ++d) {
                float2 q2 = *reinterpret_cast<const float2*>(&sm.sQt[d][r0]);  // warp broadcast
                float4 kA = *reinterpret_cast<const float4*>(&sm.sKV[d * TN + c0]);
                float4 kB = *reinterpret_cast<const float4*>(&sm.sKV[d * TN + c0 + 4]);
                a00 += q2.x * kA.x;  a01 += q2.x * kA.y;  a02 += q2.x * kA.z;  a03 += q2.x * kA.w;
                a04 += q2.x * kB.x;  a05 += q2.x * kB.y;  a06 += q2.x * kB.z;  a07 += q2.x * kB.w;
                a10 += q2.y * kA.x;  a11 += q2.y * kA.y;  a12 += q2.y * kA.z;  a13 += q2.y * kA.w;
                a14 += q2.y * kB.x;  a15 += q2.y * kB.y;  a16 += q2.y * kB.z;  a17 += q2.y * kB.w;
            }

            uchar4 mA = *reinterpret_cast<const uchar4*>(Mk + t0 + c0);
            uchar4 mB = *reinterpret_cast<const uchar4*>(Mk + t0 + c0 + 4);
            float4 s0A, s0B, s1A, s1B;
            s0A.x = mA.x ? -1e9f : a00 * scale;   s1A.x = mA.x ? -1e9f : a10 * scale;
            s0A.y = mA.y ? -1e9f : a01 * scale;   s1A.y = mA.y ? -1e9f : a11 * scale;
            s0A.z = mA.z ? -1e9f : a02 * scale;   s1A.z = mA.z ? -1e9f : a12 * scale;
            s0A.w = mA.w ? -1e9f : a03 * scale;   s1A.w = mA.w ? -1e9f : a13 * scale;
            s0B.x = mB.x ? -1e9f : a04 * scale;   s1B.x = mB.x ? -1e9f : a14 * scale;
            s0B.y = mB.y ? -1e9f : a05 * scale;   s1B.y = mB.y ? -1e9f : a15 * scale;
            s0B.z = mB.z ? -1e9f : a06 * scale;   s1B.z = mB.z ? -1e9f : a16 * scale;
            s0B.w = mB.w ? -1e9f : a07 * scale;   s1B.w = mB.w ? -1e9f : a17 * scale;
            *reinterpret_cast<float4*>(&sm.sS[r0    ][t0 + c0    ]) = s0A;
            *reinterpret_cast<float4*>(&sm.sS[r0    ][t0 + c0 + 4]) = s0B;
            *reinterpret_cast<float4*>(&sm.sS[r0 + 1][t0 + c0    ]) = s1A;
            *reinterpret_cast<float4*>(&sm.sS[r0 + 1][t0 + c0 + 4]) = s1B;
        }
    }
    __syncthreads();

    // ---------- Phase 2: row softmax stats, p = exp(s - m) in place ----------
    {
        const int warp = tid >> 5, lane = tid & 31;
        #pragma unroll
        for (int rr = 0; rr < 2; ++rr) {
            int r = warp * 2 + rr;
            float m = -3.4e38f;
            for (int i = lane * 4; i < SQ; i += 128) {
                float4 sv = *reinterpret_cast<const float4*>(&sm.sS[r][i]);
                m = fmaxf(m, fmaxf(fmaxf(sv.x, sv.y), fmaxf(sv.z, sv.w)));
            }
            #pragma unroll
            for (int o = 16; o > 0; o >>= 1) m = fmaxf(m, __shfl_xor_sync(0xffffffffu, m, o));

            float l = 0.f;
            for (int i = lane * 4; i < SQ; i += 128) {
                float4 sv = *reinterpret_cast<float4*>(&sm.sS[r][i]);
                sv.x = __expf(sv.x - m);
                sv.y = __expf(sv.y - m);
                sv.z = __expf(sv.z - m);
                sv.w = __expf(sv.w - m);
                l += (sv.x + sv.y) + (sv.z + sv.w);
                *reinterpret_cast<float4*>(&sm.sS[r][i]) = sv;
            }
            #pragma unroll
            for (int o = 16; o > 0; o >>= 1) l += __shfl_xor_sync(0xffffffffu, l, o);
            if (lane == 0) sm.sInv[r] = 1.0f / l;
        }
    }
    __syncthreads();

    // ---------- Phase 2b: write attn = p * inv_l (coalesced float4 stores) ----------
    {
        int r = tid >> 4;                   // 0..15
        float inv = sm.sInv[r];
        float* __restrict__ dst = out_attn + ((size_t)bh * SQ + row0 + r) * SQ;
        for (int i = (tid & 15) * 4; i < SQ; i += 64) {
            float4 p = *reinterpret_cast<const float4*>(&sm.sS[r][i]);
            p.x *= inv; p.y *= inv; p.z *= inv; p.w *= inv;
            *reinterpret_cast<float4*>(&dst[i]) = p;
        }
    }

    // ---------- Phase 3: context = (p @ V) * inv_l ----------
    // Per-thread: 2 rows x 8 cols, 4-way split of the t-dimension.
    // Thread map: cg3 = tid&7 (cols cg3*8..+7), rg3 = (tid>>3)&7 (rows rg3*2,+1),
    //             g3 = tid>>6 (t sub-range g3*64..+63 within each 256-tile).
    {
        const int cg3 = tid & 7;
        const int rg3 = (tid >> 3) & 7;
        const int g3  = tid >> 6;
        const int pr0 = rg3 * 2;
        const int cc0 = cg3 * 8;

        float c00=0.f,c01=0.f,c02=0.f,c03=0.f,c04=0.f,c05=0.f,c06=0.f,c07=0.f;
        float c10=0.f,c11=0.f,c12=0.f,c13=0.f,c14=0.f,c15=0.f,c16=0.f,c17=0.f;

        for (int jt = 0; jt < NTILES; ++jt) {
            __syncthreads();   // previous consumers done with sKV
            // load V tile 256 x 64 (linear copy, coalesced float4)
            #pragma unroll
            for (int i = tid * 4; i < TN * DK; i += NTHREADS * 4) {
                *reinterpret_cast<float4*>(&sm.sKV[i]) =
                    *reinterpret_cast<const float4*>(V + (size_t)jt * TN * DK + i);
            }
            __syncthreads();

            const float* __restrict__ p0 = &sm.sS[pr0    ][jt * TN + g3 * 64];
            const float* __restrict__ p1 = &sm.sS[pr0 + 1][jt * TN + g3 * 64];
            const float* __restrict__ vb = &sm.sKV[g3 * 64 * DK + cc0];

            #pragma unroll 2
            for (int tt = 0; tt < 64; tt += 4) {
                float4 P0 = *reinterpret_cast<const float4*>(&p0[tt]);
                float4 P1 = *reinterpret_cast<const float4*>(&p1[tt]);

                #define PV_STEP(PA, PB, TOFF)                                          \
                {                                                                      \
                    float4 vA = *reinterpret_cast<const float4*>(&vb[(tt + (TOFF)) * DK]);     \
                    float4 vB = *reinterpret_cast<const float4*>(&vb[(tt + (TOFF)) * DK + 4]); \
                    c00 += (PA) * vA.x;  c01 += (PA) * vA.y;  c02 += (PA) * vA.z;  c03 += (PA) * vA.w; \
                    c04 += (PA) * vB.x;  c05 += (PA) * vB.y;  c06 += (PA) * vB.z;  c07 += (PA) * vB.w; \
                    c10 += (PB) * vA.x;  c11 += (PB) * vA.y;  c12 += (PB) * vA.z;  c13 += (PB) * vA.w; \
                    c14 += (PB) * vB.x;  c15 += (PB) * vB.y;  c16 += (PB) * vB.z;  c17 += (PB) * vB.w; \
                }
                PV_STEP(P0.x, P1.x, 0)
                PV_STEP(P0.y, P1.y, 1)
                PV_STEP(P0.z, P1.z, 2)
                PV_STEP(P0.w, P1.w, 3)
                #undef PV_STEP
            }
        }

        // ---- reduce the 4 K-split partials through smem (reuse sKV) ----
        __syncthreads();                       // all warps done reading V tile
        float* __restrict__ pbuf = sm.sKV;     // [4][16][64] floats = 16 KB
        {
            float* d0 = &pbuf[((g3 << 4) + pr0    ) * 64 + cc0];
            float* d1 = &pbuf[((g3 << 4) + pr0 + 1) * 64 + cc0];
            float4 t;
            t.x=c00; t.y=c01; t.z=c02; t.w=c03; *reinterpret_cast<float4*>(d0)     = t;
            t.x=c04; t.y=c05; t.z=c06; t.w=c07; *reinterpret_cast<float4*>(d0 + 4) = t;
            t.x=c10; t.y=c11; t.z=c12; t.w=c13; *reinterpret_cast<float4*>(d1)     = t;
            t.x=c14; t.y=c15; t.z=c16; t.w=c17; *reinterpret_cast<float4*>(d1 + 4) = t;
        }
        __syncthreads();

        #pragma unroll
        for (int kk = 0; kk < 4; ++kk) {
            int oi  = tid + kk * NTHREADS;     // 0..1023
            int row = oi >> 6;                 // 0..15
            int col = oi & 63;                 // 0..63
            float s = pbuf[(     row) * 64 + col]
                    + pbuf[(16 + row) * 64 + col]
                    + pbuf[(32 + row) * 64 + col]
                    + pbuf[(48 + row) * 64 + col];
            out_ctx[((size_t)bh * SQ + row0 + row) * DK + col] = s * sm.sInv[row];
        }
    }
}

extern "C" void kernel_launch(void* const* d_in, const int* in_sizes, int n_in,
                              void* d_out, int out_size)
{
    const float* q = (const float*)d_in[0];
    const float* k = (const float*)d_in[1];
    const float* v = (const float*)d_in[2];
    const unsigned char* mraw = (const unsigned char*)d_in[3];

    float* out = (float*)d_out;
    float* out_ctx  = out;                                   // [B,H,S,D]
    float* out_attn = out + (size_t)NBH * SQ * DK;           // [B,H,S,S]

    // Canonicalize mask dtype -> uint8 g_mask (same stream => ordered).
    mask_canon_kernel<<<1, NTHREADS>>>(mraw);

    const int smem_bytes = (int)sizeof(Smem);
    cudaFuncSetAttribute(sdpa_fp32_kernel,
                         cudaFuncAttributeMaxDynamicSharedMemorySize, smem_bytes);

    dim3 grid(SQ / TM, NBH);   // (128, 64) = 8192 CTAs
    sdpa_fp32_kernel<<<grid, NTHREADS, smem_bytes>>>(q, k, v, out_ctx, out_attn);
}

// round 12
// speedup vs baseline: 2.3205x; 2.3205x over previous
#include <cuda_runtime.h>
#include <cstdint>

// Problem constants
#define SQ   2048
#define DK   64
#define NBH  64
#define NB   4
#define TM   16          // query rows per CTA
#define TN   256         // key/value cols per tile
#define NTHREADS 256
#define NTILES (SQ / TN) // 8

// Padded strides (floats) — chosen for conflict-free MMA fragment loads
#define SS_STRIDE 2052   // sS: bank = (4*gid + tig + t) conflict-free; 2052*4 % 16 == 0
#define KT_STRIDE 264    // K tile [64][264]: bank = 8*tig + gid  (distinct)
#define VT_STRIDE 72     // V tile [256][72]: bank = 8*tig + gid  (distinct)
#define QT_STRIDE 72

__device__ unsigned char g_mask[NB * SQ];

// ---------------------------------------------------------------------------
// Mask canonicalization (dtype-agnostic -> uint8 0/1). Unchanged (proven R7).
// ---------------------------------------------------------------------------
__global__ void mask_canon_kernel(const unsigned char* __restrict__ mraw)
{
    __shared__ int flagGT1, flagOff;
    const int tid = threadIdx.x;
    if (tid == 0) { flagGT1 = 0; flagOff = 0; }
    __syncthreads();

    int lGT1 = 0, lOff = 0;
    for (int i = tid; i < NB * SQ; i += NTHREADS) {
        unsigned char b = mraw[i];
        if (b > 1)        lGT1 = 1;
        if ((i & 3) && b) lOff = 1;
    }
    if (lGT1) atomicOr(&flagGT1, 1);
    if (lOff) atomicOr(&flagOff, 1);
    __syncthreads();

    if (flagGT1) {
        const float* mf = reinterpret_cast<const float*>(mraw);
        for (int i = tid; i < NB * SQ; i += NTHREADS)
            g_mask[i] = (mf[i] != 0.0f) ? 1 : 0;
    } else if (flagOff) {
        for (int i = tid; i < NB * SQ; i += NTHREADS)
            g_mask[i] = mraw[i] ? 1 : 0;
    } else {
        const int* mi = reinterpret_cast<const int*>(mraw);
        for (int i = tid; i < NB * SQ; i += NTHREADS)
            g_mask[i] = (mi[i] != 0) ? 1 : 0;
    }
}

// Shared memory (~209.7 KB)
struct Smem {
    float sS[TM * SS_STRIDE];                                   // 131,328 B
    union { float sK[64 * KT_STRIDE]; float sV[TN * VT_STRIDE]; }; // 73,728 B
    float sQ[TM * QT_STRIDE];                                   //   4,608 B
    float sInv[TM];
};

__device__ __forceinline__ uint32_t f2tf32_rna(float x) {
    uint32_t r;
    asm("cvt.rna.tf32.f32 %0, %1;" : "=r"(r) : "f"(x));
    return r;
}

__device__ __forceinline__ float rna_f(float x) {
    return __uint_as_float(f2tf32_rna(x));
}

__device__ __forceinline__ void mma_tf32(float& d0, float& d1, float& d2, float& d3,
                                         uint32_t a0, uint32_t a1, uint32_t a2, uint32_t a3,
                                         uint32_t b0, uint32_t b1)
{
    asm volatile(
        "mma.sync.aligned.m16n8k8.row.col.f32.tf32.tf32.f32 "
        "{%0,%1,%2,%3}, {%4,%5,%6,%7}, {%8,%9}, {%0,%1,%2,%3};\n"
        : "+f"(d0), "+f"(d1), "+f"(d2), "+f"(d3)
        : "r"(a0), "r"(a1), "r"(a2), "r"(a3), "r"(b0), "r"(b1));
}

__global__ __launch_bounds__(NTHREADS, 1)
void sdpa_tc_kernel(const float* __restrict__ q,
                    const float* __restrict__ k,
                    const float* __restrict__ v,
                    float* __restrict__ out_ctx,
                    float* __restrict__ out_attn)
{
    extern __shared__ char smem_raw[];
    Smem& sm = *reinterpret_cast<Smem*>(smem_raw);

    const int bh   = blockIdx.y;
    const int row0 = blockIdx.x * TM;
    const int b    = bh >> 4;
    const int tid  = threadIdx.x;
    const int warp = tid >> 5;
    const int lane = tid & 31;
    const int gid  = lane >> 2;   // 0..7
    const int tig  = lane & 3;    // 0..3

    const float* __restrict__ Q  = q + (size_t)bh * SQ * DK;
    const float* __restrict__ K  = k + (size_t)bh * DK * SQ;   // [d][t]
    const float* __restrict__ V  = v + (size_t)bh * SQ * DK;   // [t][d]
    const unsigned char* __restrict__ Mk = g_mask + (size_t)b * SQ;

    // ---------- Load Q tile (16 x 64) into sQ [16][72] ----------
    {
        int r  = tid & 15;
        int d0 = (tid >> 4) * 4;
        float4 qv = *reinterpret_cast<const float4*>(Q + (size_t)(row0 + r) * DK + d0);
        float* dst = &sm.sQ[r * QT_STRIDE + d0];
        dst[0] = qv.x; dst[1] = qv.y; dst[2] = qv.z; dst[3] = qv.w;
    }
    __syncthreads();

    // ---------- Preload Q as tf32 hi/lo fragments (error-corrected A) ----------
    // a0:(gid, c) a1:(gid+8, c) a2:(gid, c+4) a3:(gid+8, c+4), c = kc*8+tig
    uint32_t aqh[8][4], aql[8][4];
    #pragma unroll
    for (int kc = 0; kc < 8; ++kc) {
        #pragma unroll
        for (int e = 0; e < 4; ++e) {
            int r = (e & 1) ? gid + 8 : gid;
            int c = kc * 8 + tig + ((e & 2) ? 4 : 0);
            float x = sm.sQ[r * QT_STRIDE + c];
            uint32_t h = f2tf32_rna(x);
            aqh[kc][e] = h;
            aql[kc][e] = f2tf32_rna(x - __uint_as_float(h));
        }
    }

    // ---------- Phase 1: scores = (Q K) * scale, masked -> sS ----------
    const float scale = 0.125f;
    for (int jt = 0; jt < NTILES; ++jt) {
        const int t0 = jt * TN;
        __syncthreads();   // previous tile's b-loads done
        // Fill K tile [64][264], RNA-rounded to tf32 grid, coalesced float4 reads
        #pragma unroll
        for (int i = tid; i < (64 * TN) / 4; i += NTHREADS) {
            int d  = i >> 6;
            int c4 = (i & 63) << 2;
            float4 kv = *reinterpret_cast<const float4*>(K + (size_t)d * SQ + t0 + c4);
            float* dst = &sm.sK[d * KT_STRIDE + c4];
            dst[0] = rna_f(kv.x); dst[1] = rna_f(kv.y);
            dst[2] = rna_f(kv.z); dst[3] = rna_f(kv.w);
        }
        __syncthreads();

        const int nbase = warp * 32;
        #pragma unroll
        for (int nb = 0; nb < 4; ++nb) {
            const int n0 = nbase + nb * 8;
            float c0 = 0.f, c1 = 0.f, c2 = 0.f, c3 = 0.f;
            #pragma unroll
            for (int kc = 0; kc < 8; ++kc) {
                uint32_t b0 = __float_as_uint(sm.sK[(kc * 8 + tig    ) * KT_STRIDE + n0 + gid]);
                uint32_t b1 = __float_as_uint(sm.sK[(kc * 8 + tig + 4) * KT_STRIDE + n0 + gid]);
                mma_tf32(c0, c1, c2, c3, aqh[kc][0], aqh[kc][1], aqh[kc][2], aqh[kc][3], b0, b1);
                mma_tf32(c0, c1, c2, c3, aql[kc][0], aql[kc][1], aql[kc][2], aql[kc][3], b0, b1);
            }
            // mask + scale + store (rows gid, gid+8; cols n0+2tig, +1)
            const int tc0 = t0 + n0 + 2 * tig;
            unsigned char m0 = Mk[tc0], m1 = Mk[tc0 + 1];
            float2 s0, s1;
            s0.x = m0 ? -1e9f : c0 * scale;
            s0.y = m1 ? -1e9f : c1 * scale;
            s1.x = m0 ? -1e9f : c2 * scale;
            s1.y = m1 ? -1e9f : c3 * scale;
            *reinterpret_cast<float2*>(&sm.sS[ gid      * SS_STRIDE + tc0]) = s0;
            *reinterpret_cast<float2*>(&sm.sS[(gid + 8) * SS_STRIDE + tc0]) = s1;
        }
    }
    __syncthreads();

    // ---------- Phase 2: row softmax stats, p = exp(s - m) in place ----------
    {
        #pragma unroll
        for (int rr = 0; rr < 2; ++rr) {
            int r = warp * 2 + rr;
            float* row = &sm.sS[r * SS_STRIDE];
            float m = -3.4e38f;
            for (int i = lane * 4; i < SQ; i += 128) {
                float4 sv = *reinterpret_cast<const float4*>(&row[i]);
                m = fmaxf(m, fmaxf(fmaxf(sv.x, sv.y), fmaxf(sv.z, sv.w)));
            }
            #pragma unroll
            for (int o = 16; o > 0; o >>= 1) m = fmaxf(m, __shfl_xor_sync(0xffffffffu, m, o));

            float l = 0.f;
            for (int i = lane * 4; i < SQ; i += 128) {
                float4 sv = *reinterpret_cast<float4*>(&row[i]);
                sv.x = __expf(sv.x - m);
                sv.y = __expf(sv.y - m);
                sv.z = __expf(sv.z - m);
                sv.w = __expf(sv.w - m);
                l += (sv.x + sv.y) + (sv.z + sv.w);
                *reinterpret_cast<float4*>(&row[i]) = sv;
            }
            #pragma unroll
            for (int o = 16; o > 0; o >>= 1) l += __shfl_xor_sync(0xffffffffu, l, o);
            if (lane == 0) sm.sInv[r] = 1.0f / l;
        }
    }
    __syncthreads();

    // ---------- Phase 2b: write attn = p * inv_l (coalesced float4 stores) ----------
    {
        int r = tid >> 4;
        float inv = sm.sInv[r];
        const float* src = &sm.sS[r * SS_STRIDE];
        float* __restrict__ dst = out_attn + ((size_t)bh * SQ + row0 + r) * SQ;
        for (int i = (tid & 15) * 4; i < SQ; i += 64) {
            float4 p = *reinterpret_cast<const float4*>(&src[i]);
            p.x *= inv; p.y *= inv; p.z *= inv; p.w *= inv;
            *reinterpret_cast<float4*>(&dst[i]) = p;
        }
    }

    // ---------- Phase 3: context = (p @ V) * inv_l via tf32 MMA ----------
    // Per warp: output cols n0..n0+7 (d-dim), rows all 16, k over full 2048.
    {
        const int n0 = warp * 8;
        float d0 = 0.f, d1 = 0.f, d2 = 0.f, d3 = 0.f;

        for (int jt = 0; jt < NTILES; ++jt) {
            __syncthreads();   // previous V consumers done (first iter: K consumers long done)
            // Fill V tile [256][72], RNA-rounded, coalesced float4 reads
            #pragma unroll
            for (int i = tid; i < (TN * DK) / 4; i += NTHREADS) {
                int t  = i >> 4;
                int d4 = (i & 15) << 2;
                float4 vv = *reinterpret_cast<const float4*>(V + ((size_t)jt * TN + t) * DK + d4);
                float* dst = &sm.sV[t * VT_STRIDE + d4];
                dst[0] = rna_f(vv.x); dst[1] = rna_f(vv.y);
                dst[2] = rna_f(vv.z); dst[3] = rna_f(vv.w);
            }
            __syncthreads();

            #pragma unroll 4
            for (int kc = 0; kc < TN / 8; ++kc) {
                const int kb = kc * 8;
                const float* pr = &sm.sS[gid * SS_STRIDE + jt * TN + kb + tig];
                uint32_t a0 = __float_as_uint(pr[0]);                  // (gid,   k+tig)
                uint32_t a1 = __float_as_uint(pr[8 * SS_STRIDE]);      // (gid+8, k+tig)
                uint32_t a2 = __float_as_uint(pr[4]);                  // (gid,   k+tig+4)
                uint32_t a3 = __float_as_uint(pr[8 * SS_STRIDE + 4]);  // (gid+8, k+tig+4)
                uint32_t b0 = __float_as_uint(sm.sV[(kb + tig    ) * VT_STRIDE + n0 + gid]);
                uint32_t b1 = __float_as_uint(sm.sV[(kb + tig + 4) * VT_STRIDE + n0 + gid]);
                mma_tf32(d0, d1, d2, d3, a0, a1, a2, a3, b0, b1);
            }
        }

        // Epilogue: rows gid, gid+8; cols n0+2tig, +1
        float inv0 = sm.sInv[gid];
        float inv1 = sm.sInv[gid + 8];
        float2 o0; o0.x = d0 * inv0; o0.y = d1 * inv0;
        float2 o1; o1.x = d2 * inv1; o1.y = d3 * inv1;
        float* __restrict__ c0p = out_ctx + ((size_t)bh * SQ + row0 + gid) * DK + n0 + 2 * tig;
        *reinterpret_cast<float2*>(c0p)          = o0;
        *reinterpret_cast<float2*>(c0p + 8 * DK) = o1;
    }
}

extern "C" void kernel_launch(void* const* d_in, const int* in_sizes, int n_in,
                              void* d_out, int out_size)
{
    const float* q = (const float*)d_in[0];
    const float* k = (const float*)d_in[1];
    const float* v = (const float*)d_in[2];
    const unsigned char* mraw = (const unsigned char*)d_in[3];

    float* out = (float*)d_out;
    float* out_ctx  = out;                           // [B,H,S,D]
    float* out_attn = out + (size_t)NBH * SQ * DK;   // [B,H,S,S]

    mask_canon_kernel<<<1, NTHREADS>>>(mraw);

    const int smem_bytes = (int)sizeof(Smem);
    cudaFuncSetAttribute(sdpa_tc_kernel,
                         cudaFuncAttributeMaxDynamicSharedMemorySize, smem_bytes);

    dim3 grid(SQ / TM, NBH);   // (128, 64)
    sdpa_tc_kernel<<<grid, NTHREADS, smem_bytes>>>(q, k, v, out_ctx, out_attn);
}

// round 14
// speedup vs baseline: 2.7275x; 1.1754x over previous
#include <cuda_runtime.h>
#include <cstdint>

// Problem constants
#define SQ   2048
#define DK   64
#define NBH  64
#define NB   4
#define TM   16          // query rows per CTA
#define TN   128         // key/value cols per tile
#define NTHREADS 256
#define NTILES (SQ / TN) // 16

// Padded strides (floats) — conflict-free MMA fragment loads
#define SS_STRIDE 2052   // bank = 4*gid + tig (+off) distinct; rows 16B-aligned
#define KT_STRIDE 136    // K tile [64][136]: bank = 8*tig + gid + n0 distinct
#define VT_STRIDE 72     // V tile [128][72]: bank = 8*tig + gid + n0 distinct
#define QT_STRIDE 72

__device__ unsigned char g_mask[NB * SQ];

// ---------------------------------------------------------------------------
// Mask canonicalization (dtype-agnostic -> uint8 0/1). Proven since R7.
// ---------------------------------------------------------------------------
__global__ void mask_canon_kernel(const unsigned char* __restrict__ mraw)
{
    __shared__ int flagGT1, flagOff;
    const int tid = threadIdx.x;
    if (tid == 0) { flagGT1 = 0; flagOff = 0; }
    __syncthreads();

    int lGT1 = 0, lOff = 0;
    for (int i = tid; i < NB * SQ; i += NTHREADS) {
        unsigned char b = mraw[i];
        if (b > 1)        lGT1 = 1;
        if ((i & 3) && b) lOff = 1;
    }
    if (lGT1) atomicOr(&flagGT1, 1);
    if (lOff) atomicOr(&flagOff, 1);
    __syncthreads();

    if (flagGT1) {
        const float* mf = reinterpret_cast<const float*>(mraw);
        for (int i = tid; i < NB * SQ; i += NTHREADS)
            g_mask[i] = (mf[i] != 0.0f) ? 1 : 0;
    } else if (flagOff) {
        for (int i = tid; i < NB * SQ; i += NTHREADS)
            g_mask[i] = mraw[i] ? 1 : 0;
    } else {
        const int* mi = reinterpret_cast<const int*>(mraw);
        for (int i = tid; i < NB * SQ; i += NTHREADS)
            g_mask[i] = (mi[i] != 0) ? 1 : 0;
    }
}

// Shared memory (~173 KB)
struct Smem {
    float sS[TM * SS_STRIDE];                                      // 131,328 B
    union { float sK[64 * KT_STRIDE]; float sV[TN * VT_STRIDE]; }; //  36,864 B
    float sQ[TM * QT_STRIDE];                                      //   4,608 B
    float sInv[TM];
};

__device__ __forceinline__ uint32_t f2tf32_rna(float x) {
    uint32_t r;
    asm("cvt.rna.tf32.f32 %0, %1;" : "=r"(r) : "f"(x));
    return r;
}
__device__ __forceinline__ float rna_f(float x) {
    return __uint_as_float(f2tf32_rna(x));
}

__device__ __forceinline__ void mma_tf32(float& d0, float& d1, float& d2, float& d3,
                                         uint32_t a0, uint32_t a1, uint32_t a2, uint32_t a3,
                                         uint32_t b0, uint32_t b1)
{
    asm volatile(
        "mma.sync.aligned.m16n8k8.row.col.f32.tf32.tf32.f32 "
        "{%0,%1,%2,%3}, {%4,%5,%6,%7}, {%8,%9}, {%0,%1,%2,%3};\n"
        : "+f"(d0), "+f"(d1), "+f"(d2), "+f"(d3)
        : "r"(a0), "r"(a1), "r"(a2), "r"(a3), "r"(b0), "r"(b1));
}

__global__ __launch_bounds__(NTHREADS, 1)
void sdpa_tc_kernel(const float* __restrict__ q,
                    const float* __restrict__ k,
                    const float* __restrict__ v,
                    float* __restrict__ out_ctx,
                    float* __restrict__ out_attn)
{
    extern __shared__ char smem_raw[];
    Smem& sm = *reinterpret_cast<Smem*>(smem_raw);

    const int bh   = blockIdx.y;
    const int row0 = blockIdx.x * TM;
    const int b    = bh >> 4;
    const int tid  = threadIdx.x;
    const int warp = tid >> 5;
    const int lane = tid & 31;
    const int gid  = lane >> 2;   // 0..7
    const int tig  = lane & 3;    // 0..3

    const float* __restrict__ Q  = q + (size_t)bh * SQ * DK;
    const float* __restrict__ K  = k + (size_t)bh * DK * SQ;   // [d][t]
    const float* __restrict__ V  = v + (size_t)bh * SQ * DK;   // [t][d]
    const unsigned char* __restrict__ Mk = g_mask + (size_t)b * SQ;

    // ---------- Load Q tile (16 x 64) into sQ ----------
    {
        int r  = tid & 15;
        int d0 = (tid >> 4) * 4;
        float4 qv = *reinterpret_cast<const float4*>(Q + (size_t)(row0 + r) * DK + d0);
        float* dst = &sm.sQ[r * QT_STRIDE + d0];
        dst[0] = qv.x; dst[1] = qv.y; dst[2] = qv.z; dst[3] = qv.w;
    }
    __syncthreads();

    // ---------- Preload Q as RNA tf32 fragments ----------
    uint32_t aq[8][4];
    #pragma unroll
    for (int kc = 0; kc < 8; ++kc) {
        #pragma unroll
        for (int e = 0; e < 4; ++e) {
            int r = (e & 1) ? gid + 8 : gid;
            int c = kc * 8 + tig + ((e & 2) ? 4 : 0);
            aq[kc][e] = f2tf32_rna(sm.sQ[r * QT_STRIDE + c]);
        }
    }

    // ---------- Phase 1: scores = (Q K) * scale, masked -> sS ----------
    // Pipelined: LDG for tile jt+1 issued before computing tile jt.
    {
        const float scale = 0.125f;
        float4 stg[8];                       // staged K tile (raw fp32)
        // prologue: LDG tile 0
        #pragma unroll
        for (int j = 0; j < 8; ++j) {
            int i  = tid + j * NTHREADS;     // float4 index
            int d  = i >> 5;                 // 32 float4 per 128-col row
            int c4 = (i & 31) << 2;
            stg[j] = *reinterpret_cast<const float4*>(K + (size_t)d * SQ + c4);
        }

        #pragma unroll 1
        for (int jt = 0; jt < NTILES; ++jt) {
            __syncthreads();   // previous tile's consumers done with sK
            // commit staged tile: cvt RNA + STS
            #pragma unroll
            for (int j = 0; j < 8; ++j) {
                int i  = tid + j * NTHREADS;
                int d  = i >> 5;
                int c4 = (i & 31) << 2;
                float* dst = &sm.sK[d * KT_STRIDE + c4];
                dst[0] = rna_f(stg[j].x); dst[1] = rna_f(stg[j].y);
                dst[2] = rna_f(stg[j].z); dst[3] = rna_f(stg[j].w);
            }
            // prefetch next tile
            if (jt + 1 < NTILES) {
                const int t1 = (jt + 1) * TN;
                #pragma unroll
                for (int j = 0; j < 8; ++j) {
                    int i  = tid + j * NTHREADS;
                    int d  = i >> 5;
                    int c4 = (i & 31) << 2;
                    stg[j] = *reinterpret_cast<const float4*>(K + (size_t)d * SQ + t1 + c4);
                }
            }
            __syncthreads();   // sK ready

            const int t0 = jt * TN;
            const int nbase = warp * 16;
            #pragma unroll
            for (int nb = 0; nb < 2; ++nb) {
                const int n0 = nbase + nb * 8;
                float c0 = 0.f, c1 = 0.f, c2 = 0.f, c3 = 0.f;
                #pragma unroll
                for (int kc = 0; kc < 8; ++kc) {
                    uint32_t b0 = __float_as_uint(sm.sK[(kc * 8 + tig    ) * KT_STRIDE + n0 + gid]);
                    uint32_t b1 = __float_as_uint(sm.sK[(kc * 8 + tig + 4) * KT_STRIDE + n0 + gid]);
                    mma_tf32(c0, c1, c2, c3, aq[kc][0], aq[kc][1], aq[kc][2], aq[kc][3], b0, b1);
                }
                const int tc0 = t0 + n0 + 2 * tig;
                unsigned char m0 = Mk[tc0], m1 = Mk[tc0 + 1];
                float2 s0, s1;
                s0.x = m0 ? -1e9f : c0 * scale;
                s0.y = m1 ? -1e9f : c1 * scale;
                s1.x = m0 ? -1e9f : c2 * scale;
                s1.y = m1 ? -1e9f : c3 * scale;
                *reinterpret_cast<float2*>(&sm.sS[ gid      * SS_STRIDE + tc0]) = s0;
                *reinterpret_cast<float2*>(&sm.sS[(gid + 8) * SS_STRIDE + tc0]) = s1;
            }
        }
    }
    __syncthreads();

    // ---------- Phase 2: softmax; p = RNA(exp(s - m)) in place ----------
    // RNA rounding here makes phase-3 a-fragment reads EXACT on the tf32 grid
    // (removes the -4.9e-4 truncation bias measured in R12).
    {
        #pragma unroll
        for (int rr = 0; rr < 2; ++rr) {
            int r = warp * 2 + rr;
            float* row = &sm.sS[r * SS_STRIDE];
            float m = -3.4e38f;
            for (int i = lane * 4; i < SQ; i += 128) {
                float4 sv = *reinterpret_cast<const float4*>(&row[i]);
                m = fmaxf(m, fmaxf(fmaxf(sv.x, sv.y), fmaxf(sv.z, sv.w)));
            }
            #pragma unroll
            for (int o = 16; o > 0; o >>= 1) m = fmaxf(m, __shfl_xor_sync(0xffffffffu, m, o));

            float l = 0.f;
            for (int i = lane * 4; i < SQ; i += 128) {
                float4 sv = *reinterpret_cast<float4*>(&row[i]);
                sv.x = rna_f(__expf(sv.x - m));
                sv.y = rna_f(__expf(sv.y - m));
                sv.z = rna_f(__expf(sv.z - m));
                sv.w = rna_f(__expf(sv.w - m));
                l += (sv.x + sv.y) + (sv.z + sv.w);
                *reinterpret_cast<float4*>(&row[i]) = sv;
            }
            #pragma unroll
            for (int o = 16; o > 0; o >>= 1) l += __shfl_xor_sync(0xffffffffu, l, o);
            if (lane == 0) sm.sInv[r] = 1.0f / l;
        }
    }
    __syncthreads();

    // ---------- Phase 2b: write attn = p * inv_l ----------
    {
        int r = tid >> 4;
        float inv = sm.sInv[r];
        const float* src = &sm.sS[r * SS_STRIDE];
        float* __restrict__ dst = out_attn + ((size_t)bh * SQ + row0 + r) * SQ;
        for (int i = (tid & 15) * 4; i < SQ; i += 64) {
            float4 p = *reinterpret_cast<const float4*>(&src[i]);
            p.x *= inv; p.y *= inv; p.z *= inv; p.w *= inv;
            *reinterpret_cast<float4*>(&dst[i]) = p;
        }
    }

    // ---------- Phase 3: context = (p @ V) * inv_l via tf32 MMA (pipelined) ----------
    {
        const int n0 = warp * 8;
        float d0 = 0.f, d1 = 0.f, d2 = 0.f, d3 = 0.f;
        float4 stg[8];                       // staged V tile (raw fp32)
        // prologue: LDG V tile 0
        #pragma unroll
        for (int j = 0; j < 8; ++j) {
            int i  = tid + j * NTHREADS;
            int t  = i >> 4;                 // 16 float4 per 64-col row
            int d4 = (i & 15) << 2;
            stg[j] = *reinterpret_cast<const float4*>(V + (size_t)t * DK + d4);
        }

        #pragma unroll 1
        for (int jt = 0; jt < NTILES; ++jt) {
            __syncthreads();   // previous tile's consumers done with sV
            // commit staged tile: cvt RNA + STS
            #pragma unroll
            for (int j = 0; j < 8; ++j) {
                int i  = tid + j * NTHREADS;
                int t  = i >> 4;
                int d4 = (i & 15) << 2;
                float* dst = &sm.sV[t * VT_STRIDE + d4];
                dst[0] = rna_f(stg[j].x); dst[1] = rna_f(stg[j].y);
                dst[2] = rna_f(stg[j].z); dst[3] = rna_f(stg[j].w);
            }
            // prefetch next tile
            if (jt + 1 < NTILES) {
                #pragma unroll
                for (int j = 0; j < 8; ++j) {
                    int i  = tid + j * NTHREADS;
                    int t  = i >> 4;
                    int d4 = (i & 15) << 2;
                    stg[j] = *reinterpret_cast<const float4*>(
                        V + ((size_t)(jt + 1) * TN + t) * DK + d4);
                }
            }
            __syncthreads();   // sV ready

            #pragma unroll 4
            for (int kc = 0; kc < TN / 8; ++kc) {
                const int kb = kc * 8;
                const float* pr = &sm.sS[gid * SS_STRIDE + jt * TN + kb + tig];
                uint32_t a0 = __float_as_uint(pr[0]);                  // (gid,   k+tig)   exact tf32
                uint32_t a1 = __float_as_uint(pr[8 * SS_STRIDE]);      // (gid+8, k+tig)
                uint32_t a2 = __float_as_uint(pr[4]);                  // (gid,   k+tig+4)
                uint32_t a3 = __float_as_uint(pr[8 * SS_STRIDE + 4]);  // (gid+8, k+tig+4)
                uint32_t b0 = __float_as_uint(sm.sV[(kb + tig    ) * VT_STRIDE + n0 + gid]);
                uint32_t b1 = __float_as_uint(sm.sV[(kb + tig + 4) * VT_STRIDE + n0 + gid]);
                mma_tf32(d0, d1, d2, d3, a0, a1, a2, a3, b0, b1);
            }
        }

        // Epilogue: rows gid, gid+8; cols n0+2tig, +1
        float inv0 = sm.sInv[gid];
        float inv1 = sm.sInv[gid + 8];
        float2 o0; o0.x = d0 * inv0; o0.y = d1 * inv0;
        float2 o1; o1.x = d2 * inv1; o1.y = d3 * inv1;
        float* __restrict__ c0p = out_ctx + ((size_t)bh * SQ + row0 + gid) * DK + n0 + 2 * tig;
        *reinterpret_cast<float2*>(c0p)          = o0;
        *reinterpret_cast<float2*>(c0p + 8 * DK) = o1;
    }
}

extern "C" void kernel_launch(void* const* d_in, const int* in_sizes, int n_in,
                              void* d_out, int out_size)
{
    const float* q = (const float*)d_in[0];
    const float* k = (const float*)d_in[1];
    const float* v = (const float*)d_in[2];
    const unsigned char* mraw = (const unsigned char*)d_in[3];

    float* out = (float*)d_out;
    float* out_ctx  = out;                           // [B,H,S,D]
    float* out_attn = out + (size_t)NBH * SQ * DK;   // [B,H,S,S]

    mask_canon_kernel<<<1, NTHREADS>>>(mraw);

    const int smem_bytes = (int)sizeof(Smem);
    cudaFuncSetAttribute(sdpa_tc_kernel,
                         cudaFuncAttributeMaxDynamicSharedMemorySize, smem_bytes);

    dim3 grid(SQ / TM, NBH);   // (128, 64)
    sdpa_tc_kernel<<<grid, NTHREADS, smem_bytes>>>(q, k, v, out_ctx, out_attn);
}

// round 15
// speedup vs baseline: 2.9991x; 1.0996x over previous
#include <cuda_runtime.h>
#include <cstdint>

// Problem constants
#define SQ   2048
#define DK   64
#define NBH  64
#define NB   4
#define TM   16          // query rows per CTA
#define TN   128         // key/value cols per tile
#define NTHREADS 256
#define NTILES (SQ / TN) // 16

// Padded strides (floats) — conflict-free MMA fragment loads
#define SS_STRIDE 2052   // bank = 4*gid + tig (+off) distinct; rows 16B-aligned
#define KT_STRIDE 136    // K tile [64][136]: bank = 8*tig + gid + n0 distinct
#define VT_STRIDE 72     // V tile [128][72]: bank = 8*tig + gid + n0 distinct
#define QT_STRIDE 72

__device__ unsigned char g_mask[NB * SQ];

// ---------------------------------------------------------------------------
// Mask canonicalization (dtype-agnostic -> uint8 0/1). Proven since R7.
// ---------------------------------------------------------------------------
__global__ void mask_canon_kernel(const unsigned char* __restrict__ mraw)
{
    __shared__ int flagGT1, flagOff;
    const int tid = threadIdx.x;
    if (tid == 0) { flagGT1 = 0; flagOff = 0; }
    __syncthreads();

    int lGT1 = 0, lOff = 0;
    for (int i = tid; i < NB * SQ; i += NTHREADS) {
        unsigned char b = mraw[i];
        if (b > 1)        lGT1 = 1;
        if ((i & 3) && b) lOff = 1;
    }
    if (lGT1) atomicOr(&flagGT1, 1);
    if (lOff) atomicOr(&flagOff, 1);
    __syncthreads();

    if (flagGT1) {
        const float* mf = reinterpret_cast<const float*>(mraw);
        for (int i = tid; i < NB * SQ; i += NTHREADS)
            g_mask[i] = (mf[i] != 0.0f) ? 1 : 0;
    } else if (flagOff) {
        for (int i = tid; i < NB * SQ; i += NTHREADS)
            g_mask[i] = mraw[i] ? 1 : 0;
    } else {
        const int* mi = reinterpret_cast<const int*>(mraw);
        for (int i = tid; i < NB * SQ; i += NTHREADS)
            g_mask[i] = (mi[i] != 0) ? 1 : 0;
    }
}

// Shared memory (~173 KB). sV region is reused as the phase-3 partial buffer
// pbuf[8 warps][16 rows][64 cols] (32 KB <= 36,864 B).
struct Smem {
    float sS[TM * SS_STRIDE];                                      // 131,328 B
    union { float sK[64 * KT_STRIDE]; float sV[TN * VT_STRIDE]; }; //  36,864 B
    float sQ[TM * QT_STRIDE];                                      //   4,608 B
    float sInv[TM];
};

__device__ __forceinline__ uint32_t f2tf32_rna(float x) {
    uint32_t r;
    asm("cvt.rna.tf32.f32 %0, %1;" : "=r"(r) : "f"(x));
    return r;
}
__device__ __forceinline__ float rna_f(float x) {
    return __uint_as_float(f2tf32_rna(x));
}

__device__ __forceinline__ void mma_tf32(float* d,
                                         uint32_t a0, uint32_t a1, uint32_t a2, uint32_t a3,
                                         uint32_t b0, uint32_t b1)
{
    asm volatile(
        "mma.sync.aligned.m16n8k8.row.col.f32.tf32.tf32.f32 "
        "{%0,%1,%2,%3}, {%4,%5,%6,%7}, {%8,%9}, {%0,%1,%2,%3};\n"
        : "+f"(d[0]), "+f"(d[1]), "+f"(d[2]), "+f"(d[3])
        : "r"(a0), "r"(a1), "r"(a2), "r"(a3), "r"(b0), "r"(b1));
}

__global__ __launch_bounds__(NTHREADS, 1)
void sdpa_tc_kernel(const float* __restrict__ q,
                    const float* __restrict__ k,
                    const float* __restrict__ v,
                    float* __restrict__ out_ctx,
                    float* __restrict__ out_attn)
{
    extern __shared__ char smem_raw[];
    Smem& sm = *reinterpret_cast<Smem*>(smem_raw);

    const int bh   = blockIdx.y;
    const int row0 = blockIdx.x * TM;
    const int b    = bh >> 4;
    const int tid  = threadIdx.x;
    const int warp = tid >> 5;
    const int lane = tid & 31;
    const int gid  = lane >> 2;   // 0..7
    const int tig  = lane & 3;    // 0..3

    const float* __restrict__ Q  = q + (size_t)bh * SQ * DK;
    const float* __restrict__ K  = k + (size_t)bh * DK * SQ;   // [d][t]
    const float* __restrict__ V  = v + (size_t)bh * SQ * DK;   // [t][d]
    const unsigned char* __restrict__ Mk = g_mask + (size_t)b * SQ;

    // ---------- Load Q tile (16 x 64) into sQ ----------
    {
        int r  = tid & 15;
        int d0 = (tid >> 4) * 4;
        float4 qv = *reinterpret_cast<const float4*>(Q + (size_t)(row0 + r) * DK + d0);
        float* dst = &sm.sQ[r * QT_STRIDE + d0];
        dst[0] = qv.x; dst[1] = qv.y; dst[2] = qv.z; dst[3] = qv.w;
    }
    __syncthreads();

    // ---------- Preload Q as RNA tf32 fragments ----------
    uint32_t aq[8][4];
    #pragma unroll
    for (int kc = 0; kc < 8; ++kc) {
        #pragma unroll
        for (int e = 0; e < 4; ++e) {
            int r = (e & 1) ? gid + 8 : gid;
            int c = kc * 8 + tig + ((e & 2) ? 4 : 0);
            aq[kc][e] = f2tf32_rna(sm.sQ[r * QT_STRIDE + c]);
        }
    }

    // ---------- Phase 1: scores = (Q K) * scale, masked -> sS ----------
    // Pipelined fills; 4 independent MMA chains (2 n-tiles x kc parity).
    {
        const float scale = 0.125f;
        float4 stg[8];
        #pragma unroll
        for (int j = 0; j < 8; ++j) {
            int i  = tid + j * NTHREADS;
            int d  = i >> 5;
            int c4 = (i & 31) << 2;
            stg[j] = *reinterpret_cast<const float4*>(K + (size_t)d * SQ + c4);
        }

        #pragma unroll 1
        for (int jt = 0; jt < NTILES; ++jt) {
            __syncthreads();
            #pragma unroll
            for (int j = 0; j < 8; ++j) {
                int i  = tid + j * NTHREADS;
                int d  = i >> 5;
                int c4 = (i & 31) << 2;
                float* dst = &sm.sK[d * KT_STRIDE + c4];
                dst[0] = rna_f(stg[j].x); dst[1] = rna_f(stg[j].y);
                dst[2] = rna_f(stg[j].z); dst[3] = rna_f(stg[j].w);
            }
            if (jt + 1 < NTILES) {
                const int t1 = (jt + 1) * TN;
                #pragma unroll
                for (int j = 0; j < 8; ++j) {
                    int i  = tid + j * NTHREADS;
                    int d  = i >> 5;
                    int c4 = (i & 31) << 2;
                    stg[j] = *reinterpret_cast<const float4*>(K + (size_t)d * SQ + t1 + c4);
                }
            }
            __syncthreads();

            const int t0 = jt * TN;
            const int nbase = warp * 16;
            float acc[2][2][4];
            #pragma unroll
            for (int nb = 0; nb < 2; ++nb)
                #pragma unroll
                for (int p = 0; p < 2; ++p)
                    #pragma unroll
                    for (int e = 0; e < 4; ++e) acc[nb][p][e] = 0.f;

            #pragma unroll
            for (int kc = 0; kc < 8; ++kc) {
                const int par = kc & 1;
                #pragma unroll
                for (int nb = 0; nb < 2; ++nb) {
                    const int n0 = nbase + nb * 8;
                    uint32_t b0 = __float_as_uint(sm.sK[(kc * 8 + tig    ) * KT_STRIDE + n0 + gid]);
                    uint32_t b1 = __float_as_uint(sm.sK[(kc * 8 + tig + 4) * KT_STRIDE + n0 + gid]);
                    mma_tf32(acc[nb][par], aq[kc][0], aq[kc][1], aq[kc][2], aq[kc][3], b0, b1);
                }
            }

            #pragma unroll
            for (int nb = 0; nb < 2; ++nb) {
                const int n0 = nbase + nb * 8;
                float c0 = acc[nb][0][0] + acc[nb][1][0];
                float c1 = acc[nb][0][1] + acc[nb][1][1];
                float c2 = acc[nb][0][2] + acc[nb][1][2];
                float c3 = acc[nb][0][3] + acc[nb][1][3];
                const int tc0 = t0 + n0 + 2 * tig;
                unsigned char m0 = Mk[tc0], m1 = Mk[tc0 + 1];
                float2 s0, s1;
                s0.x = m0 ? -1e9f : c0 * scale;
                s0.y = m1 ? -1e9f : c1 * scale;
                s1.x = m0 ? -1e9f : c2 * scale;
                s1.y = m1 ? -1e9f : c3 * scale;
                *reinterpret_cast<float2*>(&sm.sS[ gid      * SS_STRIDE + tc0]) = s0;
                *reinterpret_cast<float2*>(&sm.sS[(gid + 8) * SS_STRIDE + tc0]) = s1;
            }
        }
    }
    __syncthreads();

    // ---------- Phase 2: softmax; p = RNA(exp(s - m)) in place ----------
    {
        #pragma unroll
        for (int rr = 0; rr < 2; ++rr) {
            int r = warp * 2 + rr;
            float* row = &sm.sS[r * SS_STRIDE];
            float m = -3.4e38f;
            for (int i = lane * 4; i < SQ; i += 128) {
                float4 sv = *reinterpret_cast<const float4*>(&row[i]);
                m = fmaxf(m, fmaxf(fmaxf(sv.x, sv.y), fmaxf(sv.z, sv.w)));
            }
            #pragma unroll
            for (int o = 16; o > 0; o >>= 1) m = fmaxf(m, __shfl_xor_sync(0xffffffffu, m, o));

            float l = 0.f;
            for (int i = lane * 4; i < SQ; i += 128) {
                float4 sv = *reinterpret_cast<float4*>(&row[i]);
                sv.x = rna_f(__expf(sv.x - m));
                sv.y = rna_f(__expf(sv.y - m));
                sv.z = rna_f(__expf(sv.z - m));
                sv.w = rna_f(__expf(sv.w - m));
                l += (sv.x + sv.y) + (sv.z + sv.w);
                *reinterpret_cast<float4*>(&row[i]) = sv;
            }
            #pragma unroll
            for (int o = 16; o > 0; o >>= 1) l += __shfl_xor_sync(0xffffffffu, l, o);
            if (lane == 0) sm.sInv[r] = 1.0f / l;
        }
    }
    __syncthreads();

    // ---------- Phase 2b: write attn = p * inv_l ----------
    {
        int r = tid >> 4;
        float inv = sm.sInv[r];
        const float* src = &sm.sS[r * SS_STRIDE];
        float* __restrict__ dst = out_attn + ((size_t)bh * SQ + row0 + r) * SQ;
        for (int i = (tid & 15) * 4; i < SQ; i += 64) {
            float4 p = *reinterpret_cast<const float4*>(&src[i]);
            p.x *= inv; p.y *= inv; p.z *= inv; p.w *= inv;
            *reinterpret_cast<float4*>(&dst[i]) = p;
        }
    }

    // ---------- Phase 3: context = (p @ V) * inv_l via tf32 MMA ----------
    // k-split across warps WITHIN each tile: warp w owns k-slice [w*16, w*16+16).
    // Each warp computes full 16x64 partials -> 8 independent MMA chains.
    {
        float acc3[8][4];
        #pragma unroll
        for (int nb = 0; nb < 8; ++nb)
            #pragma unroll
            for (int e = 0; e < 4; ++e) acc3[nb][e] = 0.f;

        float4 stg[8];
        #pragma unroll
        for (int j = 0; j < 8; ++j) {
            int i  = tid + j * NTHREADS;
            int t  = i >> 4;
            int d4 = (i & 15) << 2;
            stg[j] = *reinterpret_cast<const float4*>(V + (size_t)t * DK + d4);
        }

        #pragma unroll 1
        for (int jt = 0; jt < NTILES; ++jt) {
            __syncthreads();
            #pragma unroll
            for (int j = 0; j < 8; ++j) {
                int i  = tid + j * NTHREADS;
                int t  = i >> 4;
                int d4 = (i & 15) << 2;
                float* dst = &sm.sV[t * VT_STRIDE + d4];
                dst[0] = rna_f(stg[j].x); dst[1] = rna_f(stg[j].y);
                dst[2] = rna_f(stg[j].z); dst[3] = rna_f(stg[j].w);
            }
            if (jt + 1 < NTILES) {
                #pragma unroll
                for (int j = 0; j < 8; ++j) {
                    int i  = tid + j * NTHREADS;
                    int t  = i >> 4;
                    int d4 = (i & 15) << 2;
                    stg[j] = *reinterpret_cast<const float4*>(
                        V + ((size_t)(jt + 1) * TN + t) * DK + d4);
                }
            }
            __syncthreads();

            #pragma unroll
            for (int kc2 = 0; kc2 < 2; ++kc2) {
                const int kb = warp * 16 + kc2 * 8;          // k offset within tile
                const float* pr = &sm.sS[gid * SS_STRIDE + jt * TN + kb + tig];
                uint32_t a0 = __float_as_uint(pr[0]);                  // (gid,   k+tig)  exact tf32
                uint32_t a1 = __float_as_uint(pr[8 * SS_STRIDE]);      // (gid+8, k+tig)
                uint32_t a2 = __float_as_uint(pr[4]);                  // (gid,   k+tig+4)
                uint32_t a3 = __float_as_uint(pr[8 * SS_STRIDE + 4]);  // (gid+8, k+tig+4)
                #pragma unroll
                for (int nb = 0; nb < 8; ++nb) {
                    const int n0 = nb * 8;
                    uint32_t b0 = __float_as_uint(sm.sV[(kb + tig    ) * VT_STRIDE + n0 + gid]);
                    uint32_t b1 = __float_as_uint(sm.sV[(kb + tig + 4) * VT_STRIDE + n0 + gid]);
                    mma_tf32(acc3[nb], a0, a1, a2, a3, b0, b1);
                }
            }
        }

        // ---- reduce 8 warps' partials through smem (reuse sV region) ----
        __syncthreads();                          // all V-tile reads done
        float* __restrict__ pbuf = sm.sV;         // [8][16][64] = 32 KB
        {
            float* base0 = &pbuf[((warp << 4) + gid    ) * 64 + 2 * tig];
            float* base1 = &pbuf[((warp << 4) + gid + 8) * 64 + 2 * tig];
            #pragma unroll
            for (int nb = 0; nb < 8; ++nb) {
                float2 t0, t1;
                t0.x = acc3[nb][0]; t0.y = acc3[nb][1];
                t1.x = acc3[nb][2]; t1.y = acc3[nb][3];
                *reinterpret_cast<float2*>(base0 + nb * 8) = t0;
                *reinterpret_cast<float2*>(base1 + nb * 8) = t1;
            }
        }
        __syncthreads();

        {
            int row = tid >> 4;                  // 0..15
            int col = (tid & 15) * 4;            // 0..60
            float4 s = *reinterpret_cast<const float4*>(&pbuf[row * 64 + col]);
            #pragma unroll
            for (int w = 1; w < 8; ++w) {
                float4 t = *reinterpret_cast<const float4*>(&pbuf[((w << 4) + row) * 64 + col]);
                s.x += t.x; s.y += t.y; s.z += t.z; s.w += t.w;
            }
            float inv = sm.sInv[row];
            s.x *= inv; s.y *= inv; s.z *= inv; s.w *= inv;
            *reinterpret_cast<float4*>(
                out_ctx + ((size_t)bh * SQ + row0 + row) * DK + col) = s;
        }
    }
}

extern "C" void kernel_launch(void* const* d_in, const int* in_sizes, int n_in,
                              void* d_out, int out_size)
{
    const float* q = (const float*)d_in[0];
    const float* k = (const float*)d_in[1];
    const float* v = (const float*)d_in[2];
    const unsigned char* mraw = (const unsigned char*)d_in[3];

    float* out = (float*)d_out;
    float* out_ctx  = out;                           // [B,H,S,D]
    float* out_attn = out + (size_t)NBH * SQ * DK;   // [B,H,S,S]

    mask_canon_kernel<<<1, NTHREADS>>>(mraw);

    const int smem_bytes = (int)sizeof(Smem);
    cudaFuncSetAttribute(sdpa_tc_kernel,
                         cudaFuncAttributeMaxDynamicSharedMemorySize, smem_bytes);

    dim3 grid(SQ / TM, NBH);   // (128, 64)
    sdpa_tc_kernel<<<grid, NTHREADS, smem_bytes>>>(q, k, v, out_ctx, out_attn);
}

// round 16
// speedup vs baseline: 3.7444x; 1.2485x over previous
#include <cuda_runtime.h>
#include <cstdint>

// Problem constants
#define SQ   2048
#define DK   64
#define NBH  64
#define NB   4
#define TM   16          // query rows per CTA
#define TN   128         // key/value cols per tile
#define NTHREADS 256
#define NTILES (SQ / TN) // 16

// Padded strides (floats) — conflict-free MMA fragment loads
#define SS_STRIDE 2052   // bank = 4*gid + tig (+off) distinct; rows 16B-aligned
#define KT_STRIDE 136    // K tile [64][136]: bank = 8*tig + gid + n0 distinct
#define VT_STRIDE 72     // V tile [128][72]: bank = 8*tig + gid + n0 distinct
#define QT_STRIDE 72

__device__ unsigned char g_mask[NB * SQ];

// ---------------------------------------------------------------------------
// Mask canonicalization (dtype-agnostic -> uint8 0/1). Proven since R7.
// ---------------------------------------------------------------------------
__global__ void mask_canon_kernel(const unsigned char* __restrict__ mraw)
{
    __shared__ int flagGT1, flagOff;
    const int tid = threadIdx.x;
    if (tid == 0) { flagGT1 = 0; flagOff = 0; }
    __syncthreads();

    int lGT1 = 0, lOff = 0;
    for (int i = tid; i < NB * SQ; i += NTHREADS) {
        unsigned char b = mraw[i];
        if (b > 1)        lGT1 = 1;
        if ((i & 3) && b) lOff = 1;
    }
    if (lGT1) atomicOr(&flagGT1, 1);
    if (lOff) atomicOr(&flagOff, 1);
    __syncthreads();

    if (flagGT1) {
        const float* mf = reinterpret_cast<const float*>(mraw);
        for (int i = tid; i < NB * SQ; i += NTHREADS)
            g_mask[i] = (mf[i] != 0.0f) ? 1 : 0;
    } else if (flagOff) {
        for (int i = tid; i < NB * SQ; i += NTHREADS)
            g_mask[i] = mraw[i] ? 1 : 0;
    } else {
        const int* mi = reinterpret_cast<const int*>(mraw);
        for (int i = tid; i < NB * SQ; i += NTHREADS)
            g_mask[i] = (mi[i] != 0) ? 1 : 0;
    }
}

// Shared memory (~204.8 KB). Double-buffered K/V stages; sV stage 0 is reused
// as the phase-3 partial buffer pbuf[8][16][64] (32 KB).
struct Smem {
    float sS[TM * SS_STRIDE];                 // 131,328 B
    union {
        float sK[2][64 * KT_STRIDE];          // 2 x 34,816 B
        float sV[2][TN * VT_STRIDE];          // 2 x 36,864 B
    };
    float sQ[TM * QT_STRIDE];                 //   4,608 B
    float sInv[TM];
};

__device__ __forceinline__ uint32_t f2tf32_rna(float x) {
    uint32_t r;
    asm("cvt.rna.tf32.f32 %0, %1;" : "=r"(r) : "f"(x));
    return r;
}
__device__ __forceinline__ float rna_f(float x) {
    return __uint_as_float(f2tf32_rna(x));
}

#define CP_ASYNC16(dst_u32, src_ptr) \
    asm volatile("cp.async.cg.shared.global [%0], [%1], 16;\n" \
                 :: "r"(dst_u32), "l"(src_ptr))
#define CP_COMMIT() asm volatile("cp.async.commit_group;\n" ::: "memory")
#define CP_WAIT(N)  asm volatile("cp.async.wait_group %0;\n" :: "n"(N) : "memory")

__device__ __forceinline__ void mma_tf32(float* d,
                                         uint32_t a0, uint32_t a1, uint32_t a2, uint32_t a3,
                                         uint32_t b0, uint32_t b1)
{
    asm volatile(
        "mma.sync.aligned.m16n8k8.row.col.f32.tf32.tf32.f32 "
        "{%0,%1,%2,%3}, {%4,%5,%6,%7}, {%8,%9}, {%0,%1,%2,%3};\n"
        : "+f"(d[0]), "+f"(d[1]), "+f"(d[2]), "+f"(d[3])
        : "r"(a0), "r"(a1), "r"(a2), "r"(a3), "r"(b0), "r"(b1));
}

__global__ __launch_bounds__(NTHREADS, 1)
void sdpa_tc_kernel(const float* __restrict__ q,
                    const float* __restrict__ k,
                    const float* __restrict__ v,
                    float* __restrict__ out_ctx,
                    float* __restrict__ out_attn)
{
    extern __shared__ char smem_raw[];
    Smem& sm = *reinterpret_cast<Smem*>(smem_raw);

    const int bh   = blockIdx.y;
    const int row0 = blockIdx.x * TM;
    const int b    = bh >> 4;
    const int tid  = threadIdx.x;
    const int warp = tid >> 5;
    const int lane = tid & 31;
    const int gid  = lane >> 2;   // 0..7
    const int tig  = lane & 3;    // 0..3

    const float* __restrict__ Q  = q + (size_t)bh * SQ * DK;
    const float* __restrict__ K  = k + (size_t)bh * DK * SQ;   // [d][t]
    const float* __restrict__ V  = v + (size_t)bh * SQ * DK;   // [t][d]
    const unsigned char* __restrict__ Mk = g_mask + (size_t)b * SQ;

    // Per-thread cp.async geometry (fixed across tiles)
    const int i0 = tid;                 // float4 slot base; j-th slot = i0 + j*256
    // K tile: d = i>>5, c4 = (i&31)*4 ;  V tile: t = i>>4, d4 = (i&15)*4

    // ---------- Load Q tile (16 x 64) into sQ ----------
    {
        int r  = tid & 15;
        int d0 = (tid >> 4) * 4;
        float4 qv = *reinterpret_cast<const float4*>(Q + (size_t)(row0 + r) * DK + d0);
        float* dst = &sm.sQ[r * QT_STRIDE + d0];
        dst[0] = qv.x; dst[1] = qv.y; dst[2] = qv.z; dst[3] = qv.w;
    }
    __syncthreads();

    // ---------- Preload Q as RNA tf32 fragments ----------
    uint32_t aq[8][4];
    #pragma unroll
    for (int kc = 0; kc < 8; ++kc) {
        #pragma unroll
        for (int e = 0; e < 4; ++e) {
            int r = (e & 1) ? gid + 8 : gid;
            int c = kc * 8 + tig + ((e & 2) ? 4 : 0);
            aq[kc][e] = f2tf32_rna(sm.sQ[r * QT_STRIDE + c]);
        }
    }

    // ---------- Phase 1: scores = (Q K) * scale, masked -> sS ----------
    // Double-buffered cp.async fills; raw fp32 in smem (MMA truncates to tf32).
    {
        const float scale = 0.125f;

        // prologue: issue tile 0 into stage 0
        #pragma unroll
        for (int j = 0; j < 8; ++j) {
            int i  = i0 + j * NTHREADS;
            int d  = i >> 5;
            int c4 = (i & 31) << 2;
            uint32_t dst = (uint32_t)__cvta_generic_to_shared(&sm.sK[0][d * KT_STRIDE + c4]);
            CP_ASYNC16(dst, K + (size_t)d * SQ + c4);
        }
        CP_COMMIT();

        #pragma unroll 1
        for (int jt = 0; jt < NTILES; ++jt) {
            const int stage = jt & 1;
            // issue next tile into the other stage (free since iter jt-1's end barrier)
            if (jt + 1 < NTILES) {
                const int t1 = (jt + 1) * TN;
                const int nstage = stage ^ 1;
                #pragma unroll
                for (int j = 0; j < 8; ++j) {
                    int i  = i0 + j * NTHREADS;
                    int d  = i >> 5;
                    int c4 = (i & 31) << 2;
                    uint32_t dst = (uint32_t)__cvta_generic_to_shared(
                        &sm.sK[nstage][d * KT_STRIDE + c4]);
                    CP_ASYNC16(dst, K + (size_t)d * SQ + t1 + c4);
                }
                CP_COMMIT();
                CP_WAIT(1);     // tile jt complete (next may still fly)
            } else {
                CP_WAIT(0);
            }
            __syncthreads();    // tile jt visible to all warps

            const float* __restrict__ sK = sm.sK[stage];
            const int t0 = jt * TN;
            const int nbase = warp * 16;
            float acc[2][2][4];
            #pragma unroll
            for (int nb = 0; nb < 2; ++nb)
                #pragma unroll
                for (int p = 0; p < 2; ++p)
                    #pragma unroll
                    for (int e = 0; e < 4; ++e) acc[nb][p][e] = 0.f;

            #pragma unroll
            for (int kc = 0; kc < 8; ++kc) {
                const int par = kc & 1;
                #pragma unroll
                for (int nb = 0; nb < 2; ++nb) {
                    const int n0 = nbase + nb * 8;
                    uint32_t b0 = __float_as_uint(sK[(kc * 8 + tig    ) * KT_STRIDE + n0 + gid]);
                    uint32_t b1 = __float_as_uint(sK[(kc * 8 + tig + 4) * KT_STRIDE + n0 + gid]);
                    mma_tf32(acc[nb][par], aq[kc][0], aq[kc][1], aq[kc][2], aq[kc][3], b0, b1);
                }
            }

            #pragma unroll
            for (int nb = 0; nb < 2; ++nb) {
                const int n0 = nbase + nb * 8;
                float c0 = acc[nb][0][0] + acc[nb][1][0];
                float c1 = acc[nb][0][1] + acc[nb][1][1];
                float c2 = acc[nb][0][2] + acc[nb][1][2];
                float c3 = acc[nb][0][3] + acc[nb][1][3];
                const int tc0 = t0 + n0 + 2 * tig;
                unsigned char m0 = Mk[tc0], m1 = Mk[tc0 + 1];
                float2 s0, s1;
                s0.x = m0 ? -1e9f : c0 * scale;
                s0.y = m1 ? -1e9f : c1 * scale;
                s1.x = m0 ? -1e9f : c2 * scale;
                s1.y = m1 ? -1e9f : c3 * scale;
                *reinterpret_cast<float2*>(&sm.sS[ gid      * SS_STRIDE + tc0]) = s0;
                *reinterpret_cast<float2*>(&sm.sS[(gid + 8) * SS_STRIDE + tc0]) = s1;
            }
            __syncthreads();    // stage consumed; next iter may overwrite it
        }
    }

    // ---------- Phase 2: softmax; p = RNA(exp(s - m)) in place ----------
    // RNA keeps phase-3 a-fragments exact on the tf32 grid (bias fix, R14).
    {
        #pragma unroll
        for (int rr = 0; rr < 2; ++rr) {
            int r = warp * 2 + rr;
            float* row = &sm.sS[r * SS_STRIDE];
            float m = -3.4e38f;
            for (int i = lane * 4; i < SQ; i += 128) {
                float4 sv = *reinterpret_cast<const float4*>(&row[i]);
                m = fmaxf(m, fmaxf(fmaxf(sv.x, sv.y), fmaxf(sv.z, sv.w)));
            }
            #pragma unroll
            for (int o = 16; o > 0; o >>= 1) m = fmaxf(m, __shfl_xor_sync(0xffffffffu, m, o));

            float l = 0.f;
            for (int i = lane * 4; i < SQ; i += 128) {
                float4 sv = *reinterpret_cast<float4*>(&row[i]);
                sv.x = rna_f(__expf(sv.x - m));
                sv.y = rna_f(__expf(sv.y - m));
                sv.z = rna_f(__expf(sv.z - m));
                sv.w = rna_f(__expf(sv.w - m));
                l += (sv.x + sv.y) + (sv.z + sv.w);
                *reinterpret_cast<float4*>(&row[i]) = sv;
            }
            #pragma unroll
            for (int o = 16; o > 0; o >>= 1) l += __shfl_xor_sync(0xffffffffu, l, o);
            if (lane == 0) sm.sInv[r] = 1.0f / l;
        }
    }
    __syncthreads();

    // ---------- Phase 2b: write attn = p * inv_l ----------
    {
        int r = tid >> 4;
        float inv = sm.sInv[r];
        const float* src = &sm.sS[r * SS_STRIDE];
        float* __restrict__ dst = out_attn + ((size_t)bh * SQ + row0 + r) * SQ;
        for (int i = (tid & 15) * 4; i < SQ; i += 64) {
            float4 p = *reinterpret_cast<const float4*>(&src[i]);
            p.x *= inv; p.y *= inv; p.z *= inv; p.w *= inv;
            *reinterpret_cast<float4*>(&dst[i]) = p;
        }
    }

    // ---------- Phase 3: context = (p @ V) * inv_l via tf32 MMA ----------
    // Warp w owns k-slice [w*16, w*16+16) of each tile; 8 independent chains.
    {
        float acc3[8][4];
        #pragma unroll
        for (int nb = 0; nb < 8; ++nb)
            #pragma unroll
            for (int e = 0; e < 4; ++e) acc3[nb][e] = 0.f;

        // prologue: issue V tile 0 into stage 0 (sV regions unused by ph2/2b)
        #pragma unroll
        for (int j = 0; j < 8; ++j) {
            int i  = i0 + j * NTHREADS;
            int t  = i >> 4;
            int d4 = (i & 15) << 2;
            uint32_t dst = (uint32_t)__cvta_generic_to_shared(&sm.sV[0][t * VT_STRIDE + d4]);
            CP_ASYNC16(dst, V + (size_t)t * DK + d4);
        }
        CP_COMMIT();

        #pragma unroll 1
        for (int jt = 0; jt < NTILES; ++jt) {
            const int stage = jt & 1;
            if (jt + 1 < NTILES) {
                const int nstage = stage ^ 1;
                #pragma unroll
                for (int j = 0; j < 8; ++j) {
                    int i  = i0 + j * NTHREADS;
                    int t  = i >> 4;
                    int d4 = (i & 15) << 2;
                    uint32_t dst = (uint32_t)__cvta_generic_to_shared(
                        &sm.sV[nstage][t * VT_STRIDE + d4]);
                    CP_ASYNC16(dst, V + ((size_t)(jt + 1) * TN + t) * DK + d4);
                }
                CP_COMMIT();
                CP_WAIT(1);
            } else {
                CP_WAIT(0);
            }
            __syncthreads();

            const float* __restrict__ sV = sm.sV[stage];
            #pragma unroll
            for (int kc2 = 0; kc2 < 2; ++kc2) {
                const int kb = warp * 16 + kc2 * 8;
                const float* pr = &sm.sS[gid * SS_STRIDE + jt * TN + kb + tig];
                uint32_t a0 = __float_as_uint(pr[0]);                  // exact tf32
                uint32_t a1 = __float_as_uint(pr[8 * SS_STRIDE]);
                uint32_t a2 = __float_as_uint(pr[4]);
                uint32_t a3 = __float_as_uint(pr[8 * SS_STRIDE + 4]);
                #pragma unroll
                for (int nb = 0; nb < 8; ++nb) {
                    const int n0 = nb * 8;
                    uint32_t b0 = __float_as_uint(sV[(kb + tig    ) * VT_STRIDE + n0 + gid]);
                    uint32_t b1 = __float_as_uint(sV[(kb + tig + 4) * VT_STRIDE + n0 + gid]);
                    mma_tf32(acc3[nb], a0, a1, a2, a3, b0, b1);
                }
            }
            __syncthreads();    // stage consumed
        }

        // ---- reduce 8 warps' partials through smem (reuse sV stage 0; last
        //      compute used stage 1, and all cp.async are drained) ----
        float* __restrict__ pbuf = sm.sV[0];      // [8][16][64] = 32 KB
        {
            float* base0 = &pbuf[((warp << 4) + gid    ) * 64 + 2 * tig];
            float* base1 = &pbuf[((warp << 4) + gid + 8) * 64 + 2 * tig];
            #pragma unroll
            for (int nb = 0; nb < 8; ++nb) {
                float2 t0, t1;
                t0.x = acc3[nb][0]; t0.y = acc3[nb][1];
                t1.x = acc3[nb][2]; t1.y = acc3[nb][3];
                *reinterpret_cast<float2*>(base0 + nb * 8) = t0;
                *reinterpret_cast<float2*>(base1 + nb * 8) = t1;
            }
        }
        __syncthreads();

        {
            int row = tid >> 4;
            int col = (tid & 15) * 4;
            float4 s = *reinterpret_cast<const float4*>(&pbuf[row * 64 + col]);
            #pragma unroll
            for (int w = 1; w < 8; ++w) {
                float4 t = *reinterpret_cast<const float4*>(&pbuf[((w << 4) + row) * 64 + col]);
                s.x += t.x; s.y += t.y; s.z += t.z; s.w += t.w;
            }
            float inv = sm.sInv[row];
            s.x *= inv; s.y *= inv; s.z *= inv; s.w *= inv;
            *reinterpret_cast<float4*>(
                out_ctx + ((size_t)bh * SQ + row0 + row) * DK + col) = s;
        }
    }
}

extern "C" void kernel_launch(void* const* d_in, const int* in_sizes, int n_in,
                              void* d_out, int out_size)
{
    const float* q = (const float*)d_in[0];
    const float* k = (const float*)d_in[1];
    const float* v = (const float*)d_in[2];
    const unsigned char* mraw = (const unsigned char*)d_in[3];

    float* out = (float*)d_out;
    float* out_ctx  = out;                           // [B,H,S,D]
    float* out_attn = out + (size_t)NBH * SQ * DK;   // [B,H,S,S]

    mask_canon_kernel<<<1, NTHREADS>>>(mraw);

    const int smem_bytes = (int)sizeof(Smem);
    cudaFuncSetAttribute(sdpa_tc_kernel,
                         cudaFuncAttributeMaxDynamicSharedMemorySize, smem_bytes);

    dim3 grid(SQ / TM, NBH);   // (128, 64)
    sdpa_tc_kernel<<<grid, NTHREADS, smem_bytes>>>(q, k, v, out_ctx, out_attn);
}